// round 16
// baseline (speedup 1.0000x reference)
#include <cuda_runtime.h>
#include <cuda_bf16.h>
#include <cstdint>

// Problem constants
#define Bn  2
#define Sn  2048
#define En  2048
#define Hn  16
#define Dn  128
#define NEn 8
#define Rn  16
#define HDn 2048
#define Mn  4096            // B*S
#define NEG_BIG -3.0e38f

// ---------------- scratch (device globals: no cudaMalloc allowed) ----------
__device__ __align__(16) float g_q[(size_t)Mn * HDn];
__device__ __align__(16) float g_k[(size_t)Mn * HDn];
__device__ __align__(16) float g_v[(size_t)Mn * HDn];

// bf16 hi/lo split operand storage
__device__ __align__(16) __nv_bfloat16 g_xhi[(size_t)Mn * En],  g_xlo[(size_t)Mn * En];
__device__ __align__(16) __nv_bfloat16 g_Whi[4][(size_t)HDn * En], g_Wlo[4][(size_t)HDn * En];
__device__ __align__(16) __nv_bfloat16 g_AXhi[4][(size_t)128 * En], g_AXlo[4][(size_t)128 * En];
__device__ __align__(16) __nv_bfloat16 g_BXhi[4][(size_t)HDn * 128], g_BXlo[4][(size_t)HDn * 128];
__device__ __align__(16) __nv_bfloat16 g_hhi[3][(size_t)Mn * 128], g_hlo[3][(size_t)Mn * 128];
__device__ __align__(16) __nv_bfloat16 g_ohi[(size_t)Mn * HDn], g_olo[(size_t)Mn * HDn];
// flash operands: q/k rope'd splits [B,S,H,D]; v^T splits [B,H,D,S]
__device__ __align__(16) __nv_bfloat16 g_qshi[(size_t)Mn * HDn], g_qslo[(size_t)Mn * HDn];
__device__ __align__(16) __nv_bfloat16 g_kshi[(size_t)Mn * HDn], g_kslo[(size_t)Mn * HDn];
__device__ __align__(16) __nv_bfloat16 g_vthi[(size_t)Mn * HDn], g_vtlo[(size_t)Mn * HDn];

// ---------------------------------------------------------------------------
// asm helpers
// ---------------------------------------------------------------------------
__device__ __forceinline__ void mma16(float* c, const uint32_t* a, const uint32_t* b) {
    asm("mma.sync.aligned.m16n8k16.row.col.f32.bf16.bf16.f32 "
        "{%0,%1,%2,%3}, {%4,%5,%6,%7}, {%8,%9}, {%0,%1,%2,%3};\n"
        : "+f"(c[0]), "+f"(c[1]), "+f"(c[2]), "+f"(c[3])
        : "r"(a[0]), "r"(a[1]), "r"(a[2]), "r"(a[3]), "r"(b[0]), "r"(b[1]));
}

__device__ __forceinline__ void ldsm4(uint32_t* r, uint32_t addr) {
    asm volatile(
        "ldmatrix.sync.aligned.m8n8.x4.shared.b16 {%0,%1,%2,%3}, [%4];"
        : "=r"(r[0]), "=r"(r[1]), "=r"(r[2]), "=r"(r[3]) : "r"(addr));
}

__device__ __forceinline__ void cp16(uint32_t saddr, const void* gaddr) {
    asm volatile("cp.async.cg.shared.global [%0], [%1], 16;\n" :: "r"(saddr), "l"(gaddr));
}
__device__ __forceinline__ void cp_commit() { asm volatile("cp.async.commit_group;\n"); }
__device__ __forceinline__ void cp_wait0()  { asm volatile("cp.async.wait_group 0;\n"); }

__device__ __forceinline__ float ex2(float x) {
    float r;
    asm("ex2.approx.f32 %0, %1;" : "=f"(r) : "f"(x));
    return r;
}

// split a,b into packed bf16x2 hi and lo fragments
__device__ __forceinline__ void packsplit(float a, float b, uint32_t& hi, uint32_t& lo) {
    __nv_bfloat162 h = __floats2bfloat162_rn(a, b);
    float ra = a - __bfloat162float(h.x);
    float rb = b - __bfloat162float(h.y);
    __nv_bfloat162 l = __floats2bfloat162_rn(ra, rb);
    hi = *(uint32_t*)&h;
    lo = *(uint32_t*)&l;
}

// ---------------------------------------------------------------------------
// batched f32 -> bf16 hi/lo split (grid-stride, z-indexed tensor set)
// ---------------------------------------------------------------------------
#define NCVT 13
struct CvtArgs {
    const float* src[NCVT];
    __nv_bfloat16* hi[NCVT];
    __nv_bfloat16* lo[NCVT];
    int n4[NCVT];
};

__global__ void cvtb_kernel(CvtArgs a)
{
    const int z = blockIdx.z;
    const int n4 = a.n4[z];
    const float4* s = (const float4*)a.src[z];
    uint2* hp = (uint2*)a.hi[z];
    uint2* lp = (uint2*)a.lo[z];
    for (int i = blockIdx.x * blockDim.x + threadIdx.x; i < n4;
         i += gridDim.x * blockDim.x) {
        float4 v = s[i];
        uint32_t h01, l01, h23, l23;
        packsplit(v.x, v.y, h01, l01);
        packsplit(v.z, v.w, h23, l23);
        hp[i] = make_uint2(h01, h23);
        lp[i] = make_uint2(l01, l23);
    }
}

// ---------------------------------------------------------------------------
// tgemm2 (bf16x3, two K-segments): C = A1 @ B1^T  +  A2 @ B2^T
//   Epilogue: +bias, *mask(expert), write float C or split bf16 Chi/Clo.
// BK = 32, 2-stage cp.async, single sync per K-chunk, ldmatrix frags.
// blockIdx.z selects pointer set (batched q/k/v).
// ---------------------------------------------------------------------------
struct GArgs {
    const __nv_bfloat16 *A1hi[3], *A1lo[3], *B1hi[3], *B1lo[3];
    const __nv_bfloat16 *A2hi[3], *A2lo[3], *B2hi[3], *B2lo[3];
    const float *bias[3], *mask[3];
    float* C[3];
    __nv_bfloat16 *Chi[3], *Clo[3];
};

template<int BM, int BN, int MT, int NT, int NW>
__global__ void __launch_bounds__(NW * 32) tgemm2_kernel(
    GArgs g, int M, int N, int K1, int K2)
{
    constexpr int NTHR  = NW * 32;
    constexpr int ROWB  = 80;                 // 40 bf16 per padded row
    constexpr int ABY   = BM * ROWB;
    constexpr int BBY   = BN * ROWB;
    constexpr int BUFB  = 2 * ABY + 2 * BBY;
    constexpr int WROWS = BM / (MT * 16);

    extern __shared__ char smraw[];
    const uint32_t sbase = (uint32_t)__cvta_generic_to_shared(smraw);

    const int z = blockIdx.z;
    const float* bias = g.bias[z];
    const float* mask = g.mask[z];
    float* C = g.C[z];
    __nv_bfloat16* Chi = g.Chi[z];
    __nv_bfloat16* Clo = g.Clo[z];

    const int bm = blockIdx.y * BM;
    const int bn = blockIdx.x * BN;
    const int tid  = threadIdx.x;
    const int lane = tid & 31;
    const int w    = tid >> 5;
    const int wm   = (w % WROWS) * (MT * 16);
    const int wn   = (w / WROWS) * (NT * 8);
    const int grp  = lane >> 2;
    const int qt   = lane & 3;

    const int a_row = ((lane >> 3) & 1) * 8 + (lane & 7);
    const int a_col = (lane >> 4) * 8;
    const int b_row = (lane >> 4) * 8 + (lane & 7);
    const int b_col = ((lane >> 3) & 1) * 8;

    const int nk1 = K1 >> 5;
    const int nk  = nk1 + (K2 >> 5);

    float acc[MT][NT][4];
#pragma unroll
    for (int mt = 0; mt < MT; mt++)
#pragma unroll
        for (int nt = 0; nt < NT; nt++)
#pragma unroll
            for (int e = 0; e < 4; e++) acc[mt][nt][e] = 0.f;

    auto issue = [&](int it, int buf) {
        const __nv_bfloat16 *pAh, *pAl, *pBh, *pBl;
        int kst, k0;
        if (it < nk1) {
            pAh = g.A1hi[z]; pAl = g.A1lo[z]; pBh = g.B1hi[z]; pBl = g.B1lo[z];
            kst = K1; k0 = it << 5;
        } else {
            pAh = g.A2hi[z]; pAl = g.A2lo[z]; pBh = g.B2hi[z]; pBl = g.B2lo[z];
            kst = K2; k0 = (it - nk1) << 5;
        }
        const uint32_t sb = sbase + buf * BUFB;
#pragma unroll
        for (int i = tid; i < BM * 4; i += NTHR) {
            int row = i >> 2, c = i & 3;
            size_t go = (size_t)(bm + row) * kst + k0 + c * 8;
            cp16(sb + row * ROWB + c * 16, pAh + go);
            cp16(sb + ABY + row * ROWB + c * 16, pAl + go);
        }
#pragma unroll
        for (int i = tid; i < BN * 4; i += NTHR) {
            int row = i >> 2, c = i & 3;
            size_t go = (size_t)(bn + row) * kst + k0 + c * 8;
            cp16(sb + 2 * ABY + row * ROWB + c * 16, pBh + go);
            cp16(sb + 2 * ABY + BBY + row * ROWB + c * 16, pBl + go);
        }
        cp_commit();
    };

    issue(0, 0);

    for (int it = 0; it < nk; it++) {
        const int buf = it & 1;
        cp_wait0();          // issue(it) landed (thread-local view)
        __syncthreads();     // all threads' data visible; all warps done with buf^1
        if (it + 1 < nk) issue(it + 1, buf ^ 1);   // overlaps with compute below

        const uint32_t aHi = sbase + buf * BUFB;
        const uint32_t aLo = aHi + ABY;
        const uint32_t bHi = aHi + 2 * ABY;
        const uint32_t bLo = bHi + BBY;

#pragma unroll
        for (int kk = 0; kk < 32; kk += 16) {
            uint32_t afH[MT][4], afL[MT][4];
#pragma unroll
            for (int mt = 0; mt < MT; mt++) {
                uint32_t off = (uint32_t)((wm + mt * 16 + a_row) * 40 + kk + a_col) * 2;
                ldsm4(afH[mt], aHi + off);
                ldsm4(afL[mt], aLo + off);
            }
#pragma unroll
            for (int nb = 0; nb < NT / 2; nb++) {
                uint32_t off = (uint32_t)((wn + nb * 16 + b_row) * 40 + kk + b_col) * 2;
                uint32_t bh[4], bl[4];
                ldsm4(bh, bHi + off);
                ldsm4(bl, bLo + off);
#pragma unroll
                for (int hf = 0; hf < 2; hf++)
#pragma unroll
                    for (int mt = 0; mt < MT; mt++)
                        mma16(acc[mt][nb * 2 + hf], afH[mt], &bl[hf * 2]);
#pragma unroll
                for (int hf = 0; hf < 2; hf++)
#pragma unroll
                    for (int mt = 0; mt < MT; mt++)
                        mma16(acc[mt][nb * 2 + hf], afL[mt], &bh[hf * 2]);
#pragma unroll
                for (int hf = 0; hf < 2; hf++)
#pragma unroll
                    for (int mt = 0; mt < MT; mt++)
                        mma16(acc[mt][nb * 2 + hf], afH[mt], &bh[hf * 2]);
            }
        }
    }

    // epilogue
#pragma unroll
    for (int mt = 0; mt < MT; mt++) {
#pragma unroll
        for (int nt = 0; nt < NT; nt++) {
            int m0 = bm + wm + mt * 16 + grp;
            int n  = bn + wn + nt * 8 + qt * 2;
            float c0 = acc[mt][nt][0], c1 = acc[mt][nt][1];
            float c2 = acc[mt][nt][2], c3 = acc[mt][nt][3];
            if (bias) {
                float b0 = bias[n], b1 = bias[n + 1];
                c0 += b0; c1 += b1; c2 += b0; c3 += b1;
            }
            if (mask) {   // h-GEMM: expert = n>>4 (R=16 contiguous)
                float s0 = mask[(size_t)m0 * NEn + (n >> 4)];
                float s1 = mask[(size_t)(m0 + 8) * NEn + (n >> 4)];
                c0 *= s0; c1 *= s0; c2 *= s1; c3 *= s1;
            }
            if (Chi) {
                uint32_t h0, l0, h1, l1;
                packsplit(c0, c1, h0, l0);
                packsplit(c2, c3, h1, l1);
                *(uint32_t*)&Chi[(size_t)m0 * N + n] = h0;
                *(uint32_t*)&Clo[(size_t)m0 * N + n] = l0;
                *(uint32_t*)&Chi[(size_t)(m0 + 8) * N + n] = h1;
                *(uint32_t*)&Clo[(size_t)(m0 + 8) * N + n] = l1;
            } else {
                *(float2*)&C[(size_t)m0 * N + n] = make_float2(c0, c1);
                *(float2*)&C[(size_t)(m0 + 8) * N + n] = make_float2(c2, c3);
            }
        }
    }
}

using KernT = void(*)(GArgs, int, int, int, int);
// dense: BM=128, BN=256, 16 warps
constexpr int DENSE_SMEM = 2 * (2 * 128 * 80 + 2 * 256 * 80);   // 122880 B
constexpr int H_SMEM     = 2 * (2 * 32 * 80 + 2 * 128 * 80);    // 51200 B

// ---------------------------------------------------------------------------
// RoPE + bf16 hi/lo split (vectorized; exp2f-based inv_freq — no FP64)
// q gets *log2(e)/sqrt(D) folded in (for exp2 softmax)
// ---------------------------------------------------------------------------
__global__ void rope_split_kernel(const float* __restrict__ q, const float* __restrict__ k,
                                  __nv_bfloat16* __restrict__ qhi, __nv_bfloat16* __restrict__ qlo,
                                  __nv_bfloat16* __restrict__ khi, __nv_bfloat16* __restrict__ klo)
{
    const int total = Bn * Sn * Hn * (Dn / 4);   // 2 freq pairs per thread
    int idx = blockIdx.x * blockDim.x + threadIdx.x;
    if (idx >= total) return;
    int i2 = (idx & 31) * 2;                     // i, i+1  (0..62 even)
    int s  = (idx >> 9) & (Sn - 1);
    const float QSC = 0.12751743f;               // log2(e)/sqrt(128)
    const float L2T = 0.20762050593045952f;      // log2(10000)/64

    float inv0 = exp2f(-(float)i2 * L2T);
    float inv1 = exp2f(-(float)(i2 + 1) * L2T);
    float c0, s0, c1, s1;
    sincosf((float)s * inv0, &s0, &c0);
    sincosf((float)s * inv1, &s1, &c1);

    size_t base = ((size_t)(idx >> 5)) * 128;
    // ---- q ----
    {
        float2 a = *(const float2*)&q[base + i2];
        float2 b = *(const float2*)&q[base + i2 + 64];
        float r0 = (a.x * c0 - b.x * s0) * QSC;
        float r1 = (a.y * c1 - b.y * s1) * QSC;
        float t0 = (b.x * c0 + a.x * s0) * QSC;
        float t1 = (b.y * c1 + a.y * s1) * QSC;
        uint32_t h, l;
        packsplit(r0, r1, h, l);
        *(uint32_t*)&qhi[base + i2] = h;
        *(uint32_t*)&qlo[base + i2] = l;
        packsplit(t0, t1, h, l);
        *(uint32_t*)&qhi[base + i2 + 64] = h;
        *(uint32_t*)&qlo[base + i2 + 64] = l;
    }
    // ---- k ----
    {
        float2 a = *(const float2*)&k[base + i2];
        float2 b = *(const float2*)&k[base + i2 + 64];
        float r0 = a.x * c0 - b.x * s0;
        float r1 = a.y * c1 - b.y * s1;
        float t0 = b.x * c0 + a.x * s0;
        float t1 = b.y * c1 + a.y * s1;
        uint32_t h, l;
        packsplit(r0, r1, h, l);
        *(uint32_t*)&khi[base + i2] = h;
        *(uint32_t*)&klo[base + i2] = l;
        packsplit(t0, t1, h, l);
        *(uint32_t*)&khi[base + i2 + 64] = h;
        *(uint32_t*)&klo[base + i2 + 64] = l;
    }
}

// ---------------------------------------------------------------------------
// V split + transpose:  v [B,S,H,D] f32  ->  vt{hi,lo} [B,H,D,S] bf16
// ---------------------------------------------------------------------------
__global__ void vsplit_kernel(const float* __restrict__ v,
                              __nv_bfloat16* __restrict__ vthi,
                              __nv_bfloat16* __restrict__ vtlo)
{
    __shared__ float tile[32][33];               // [s][d]
    const int bh = blockIdx.z;                   // b*Hn + h
    const int b  = bh >> 4, h = bh & 15;
    const int s0 = blockIdx.x * 32;
    const int d0 = blockIdx.y * 32;
    const int tid = threadIdx.x;                 // 256 threads
    const int tx = tid & 31, ty = tid >> 5;

#pragma unroll
    for (int r = 0; r < 4; r++) {
        int s = s0 + ty + r * 8;
        tile[ty + r * 8][tx] = v[(((size_t)b * Sn + s) * Hn + h) * 128 + d0 + tx];
    }
    __syncthreads();

    const int sp = tid & 15;
    const int dd = tid >> 4;
#pragma unroll
    for (int r = 0; r < 2; r++) {
        int d = dd + r * 16;
        float v0 = tile[sp * 2][d];
        float v1 = tile[sp * 2 + 1][d];
        uint32_t hi, lo;
        packsplit(v0, v1, hi, lo);
        size_t o = ((size_t)bh * 128 + d0 + d) * Sn + s0 + sp * 2;
        *(uint32_t*)&vthi[o] = hi;
        *(uint32_t*)&vtlo[o] = lo;
    }
}

// ---------------------------------------------------------------------------
// Flash attention, bf16x3 tensor cores. Single sync per tile.
// ---------------------------------------------------------------------------
#define FQH 0
#define FQL 34816
#define FKH(b) (69632 + (b) * 34816)
#define FKL(b) (FKH(b) + 17408)
#define FVH(b) (139264 + (b) * 36864)
#define FVL(b) (FVH(b) + 18432)
#define FLASH_SMEM 212992

__global__ void __launch_bounds__(256, 1) flash_kernel(
    const __nv_bfloat16* __restrict__ Qhi, const __nv_bfloat16* __restrict__ Qlo,
    const __nv_bfloat16* __restrict__ Khi, const __nv_bfloat16* __restrict__ Klo,
    const __nv_bfloat16* __restrict__ Vthi, const __nv_bfloat16* __restrict__ Vtlo,
    __nv_bfloat16* __restrict__ Ohi, __nv_bfloat16* __restrict__ Olo)
{
    extern __shared__ char smraw[];
    const uint32_t sb = (uint32_t)__cvta_generic_to_shared(smraw);

    const int qTile = gridDim.x - 1 - blockIdx.x;   // heavy CTAs first
    const int q0 = qTile * 128;
    const int h  = blockIdx.y;
    const int b  = blockIdx.z;
    const int tid  = threadIdx.x;
    const int lane = tid & 31;
    const int w    = tid >> 5;
    const int w16  = w * 16;
    const int grp  = lane >> 2;
    const int qt   = lane & 3;

    const int a_row = ((lane >> 3) & 1) * 8 + (lane & 7);
    const int a_col = (lane >> 4) * 8;
    const int b_row = (lane >> 4) * 8 + (lane & 7);
    const int b_col = ((lane >> 3) & 1) * 8;

    auto fillK = [&](int j0, int buf) {
        for (int i = tid; i < 1024; i += 256) {
            int row = i >> 4, c = i & 15;
            size_t gg = (((size_t)b * Sn + j0 + row) * Hn + h) * 128 + c * 8;
            uint32_t so = row * 272 + c * 16;
            cp16(sb + FKH(buf) + so, Khi + gg);
            cp16(sb + FKL(buf) + so, Klo + gg);
        }
    };
    auto fillV = [&](int j0, int buf) {
        for (int i = tid; i < 1024; i += 256) {
            int row = i >> 3, c = i & 7;
            size_t gg = (((size_t)(b * Hn + h)) * 128 + row) * Sn + j0 + c * 8;
            uint32_t so = row * 144 + c * 16;
            cp16(sb + FVH(buf) + so, Vthi + gg);
            cp16(sb + FVL(buf) + so, Vtlo + gg);
        }
    };

    for (int i = tid; i < 2048; i += 256) {
        int row = i >> 4, c = i & 15;
        size_t gg = (((size_t)b * Sn + q0 + row) * Hn + h) * 128 + c * 8;
        uint32_t so = row * 272 + c * 16;
        cp16(sb + FQH + so, Qhi + gg);
        cp16(sb + FQL + so, Qlo + gg);
    }
    fillK(0, 0);
    fillV(0, 0);
    cp_commit();

    float o[16][4];
#pragma unroll
    for (int t = 0; t < 16; t++)
#pragma unroll
        for (int e = 0; e < 4; e++) o[t][e] = 0.f;
    float run_m0 = NEG_BIG, run_m1 = NEG_BIG;
    float run_l0 = 0.f, run_l1 = 0.f;

    const int ntiles = qTile * 2 + 2;
    for (int t = 0; t < ntiles; t++) {
        const int buf = t & 1;
        const int j0 = t * 64;
        cp_wait0();
        __syncthreads();
        if (t + 1 < ntiles) {
            fillK((t + 1) * 64, buf ^ 1);
            fillV((t + 1) * 64, buf ^ 1);
            cp_commit();
        }

        // ---- S = Q K^T (bf16x3) ----
        float s[8][4];
#pragma unroll
        for (int tt = 0; tt < 8; tt++)
#pragma unroll
            for (int e = 0; e < 4; e++) s[tt][e] = 0.f;

        const uint32_t kh = FKH(buf), kl = FKL(buf);
#pragma unroll
        for (int kk = 0; kk < 8; kk++) {
            uint32_t qh[4], ql[4];
            uint32_t qoff = (uint32_t)((w16 + a_row) * 136 + kk * 16 + a_col) * 2;
            ldsm4(qh, sb + FQH + qoff);
            ldsm4(ql, sb + FQL + qoff);
#pragma unroll
            for (int nb = 0; nb < 4; nb++) {
                uint32_t bh[4], bl[4];
                uint32_t boff = (uint32_t)((nb * 16 + b_row) * 136 + kk * 16 + b_col) * 2;
                ldsm4(bh, sb + kh + boff);
                ldsm4(bl, sb + kl + boff);
#pragma unroll
                for (int hf = 0; hf < 2; hf++) {
                    float* c = s[nb * 2 + hf];
                    mma16(c, qh, &bl[hf * 2]);
                    mma16(c, ql, &bh[hf * 2]);
                    mma16(c, qh, &bh[hf * 2]);
                }
            }
        }

        // ---- causal mask ----
        if (j0 >= q0) {
#pragma unroll
            for (int tt = 0; tt < 8; tt++) {
#pragma unroll
                for (int e = 0; e < 4; e++) {
                    int col = j0 + tt * 8 + 2 * qt + (e & 1);
                    int row = q0 + w16 + grp + 8 * (e >> 1);
                    if (col > row) s[tt][e] = NEG_BIG;
                }
            }
        }

        // ---- online softmax (log2e units) ----
        {
            float m0 = NEG_BIG, m1 = NEG_BIG;
#pragma unroll
            for (int tt = 0; tt < 8; tt++) {
                m0 = fmaxf(m0, fmaxf(s[tt][0], s[tt][1]));
                m1 = fmaxf(m1, fmaxf(s[tt][2], s[tt][3]));
            }
            m0 = fmaxf(m0, __shfl_xor_sync(0xffffffffu, m0, 1));
            m0 = fmaxf(m0, __shfl_xor_sync(0xffffffffu, m0, 2));
            m1 = fmaxf(m1, __shfl_xor_sync(0xffffffffu, m1, 1));
            m1 = fmaxf(m1, __shfl_xor_sync(0xffffffffu, m1, 2));
            float nm0 = fmaxf(run_m0, m0), nm1 = fmaxf(run_m1, m1);
            float cr0 = ex2(run_m0 - nm0), cr1 = ex2(run_m1 - nm1);
            run_m0 = nm0; run_m1 = nm1;

            float sum0 = 0.f, sum1 = 0.f;
#pragma unroll
            for (int tt = 0; tt < 8; tt++) {
                s[tt][0] = ex2(s[tt][0] - nm0); sum0 += s[tt][0];
                s[tt][1] = ex2(s[tt][1] - nm0); sum0 += s[tt][1];
                s[tt][2] = ex2(s[tt][2] - nm1); sum1 += s[tt][2];
                s[tt][3] = ex2(s[tt][3] - nm1); sum1 += s[tt][3];
            }
            sum0 += __shfl_xor_sync(0xffffffffu, sum0, 1);
            sum0 += __shfl_xor_sync(0xffffffffu, sum0, 2);
            sum1 += __shfl_xor_sync(0xffffffffu, sum1, 1);
            sum1 += __shfl_xor_sync(0xffffffffu, sum1, 2);
            run_l0 = run_l0 * cr0 + sum0;
            run_l1 = run_l1 * cr1 + sum1;

#pragma unroll
            for (int tt = 0; tt < 16; tt++) {
                o[tt][0] *= cr0; o[tt][1] *= cr0;
                o[tt][2] *= cr1; o[tt][3] *= cr1;
            }
        }

        // ---- O += P V (bf16x3; P from accumulator registers) ----
        const uint32_t vh = FVH(buf), vl = FVL(buf);
#pragma unroll
        for (int k = 0; k < 4; k++) {
            uint32_t ph[4], pl[4];
            packsplit(s[2 * k][0],     s[2 * k][1],     ph[0], pl[0]);
            packsplit(s[2 * k][2],     s[2 * k][3],     ph[1], pl[1]);
            packsplit(s[2 * k + 1][0], s[2 * k + 1][1], ph[2], pl[2]);
            packsplit(s[2 * k + 1][2], s[2 * k + 1][3], ph[3], pl[3]);
#pragma unroll
            for (int nb = 0; nb < 8; nb++) {
                uint32_t bh[4], bl[4];
                uint32_t voff = (uint32_t)((nb * 16 + b_row) * 72 + k * 16 + b_col) * 2;
                ldsm4(bh, sb + vh + voff);
                ldsm4(bl, sb + vl + voff);
#pragma unroll
                for (int hf = 0; hf < 2; hf++) {
                    float* c = o[nb * 2 + hf];
                    mma16(c, ph, &bl[hf * 2]);
                    mma16(c, pl, &bh[hf * 2]);
                    mma16(c, ph, &bh[hf * 2]);
                }
            }
        }
    }

    // ---- epilogue: bf16 hi/lo split, [B,S,H*D] layout ----
    {
        float inv0 = 1.f / run_l0;
        float inv1 = 1.f / run_l1;
        int row0 = q0 + w16 + grp;
        size_t base0 = (((size_t)b * Sn + row0) * Hn + h) * 128 + 2 * qt;
        size_t base1 = (((size_t)b * Sn + row0 + 8) * Hn + h) * 128 + 2 * qt;
#pragma unroll
        for (int tt = 0; tt < 16; tt++) {
            uint32_t h0, l0, h1, l1;
            packsplit(o[tt][0] * inv0, o[tt][1] * inv0, h0, l0);
            packsplit(o[tt][2] * inv1, o[tt][3] * inv1, h1, l1);
            *(uint32_t*)&Ohi[base0 + tt * 8] = h0;
            *(uint32_t*)&Olo[base0 + tt * 8] = l0;
            *(uint32_t*)&Ohi[base1 + tt * 8] = h1;
            *(uint32_t*)&Olo[base1 + tt * 8] = l1;
        }
    }
}

// ---------------------------------------------------------------------------
extern "C" void kernel_launch(void* const* d_in, const int* in_sizes, int n_in,
                              void* d_out, int out_size)
{
    const float* x    = (const float*)d_in[0];
    const float* mask = (const float*)d_in[1];
    const float* Wp[4] = {(const float*)d_in[2], (const float*)d_in[6],
                          (const float*)d_in[10], (const float*)d_in[14]};
    const float* bp[4] = {(const float*)d_in[3], (const float*)d_in[7],
                          (const float*)d_in[11], (const float*)d_in[15]};
    const float* Ap[4] = {(const float*)d_in[4], (const float*)d_in[8],
                          (const float*)d_in[12], (const float*)d_in[16]};
    const float* Bp[4] = {(const float*)d_in[5], (const float*)d_in[9],
                          (const float*)d_in[13], (const float*)d_in[17]};
    float* out = (float*)d_out;

    float *gq, *gk, *gv;
    cudaGetSymbolAddress((void**)&gq, g_q);
    cudaGetSymbolAddress((void**)&gk, g_k);
    cudaGetSymbolAddress((void**)&gv, g_v);
    float* gqkv[3] = {gq, gk, gv};

    __nv_bfloat16 *xhi, *xlo, *ohi, *olo;
    __nv_bfloat16 *Whi[4], *Wlo[4], *AXhi[4], *AXlo[4], *BXhi[4], *BXlo[4];
    __nv_bfloat16 *hhi[3], *hlo[3];
    __nv_bfloat16 *qshi, *qslo, *kshi, *kslo, *vthi, *vtlo;
    {
        char *p;
        cudaGetSymbolAddress((void**)&p, g_xhi); xhi = (__nv_bfloat16*)p;
        cudaGetSymbolAddress((void**)&p, g_xlo); xlo = (__nv_bfloat16*)p;
        cudaGetSymbolAddress((void**)&p, g_ohi); ohi = (__nv_bfloat16*)p;
        cudaGetSymbolAddress((void**)&p, g_olo); olo = (__nv_bfloat16*)p;
        cudaGetSymbolAddress((void**)&p, g_qshi); qshi = (__nv_bfloat16*)p;
        cudaGetSymbolAddress((void**)&p, g_qslo); qslo = (__nv_bfloat16*)p;
        cudaGetSymbolAddress((void**)&p, g_kshi); kshi = (__nv_bfloat16*)p;
        cudaGetSymbolAddress((void**)&p, g_kslo); kslo = (__nv_bfloat16*)p;
        cudaGetSymbolAddress((void**)&p, g_vthi); vthi = (__nv_bfloat16*)p;
        cudaGetSymbolAddress((void**)&p, g_vtlo); vtlo = (__nv_bfloat16*)p;
        char *p_Wh, *p_Wl, *p_Ah, *p_Al, *p_Bh, *p_Bl, *p_hh, *p_hl;
        cudaGetSymbolAddress((void**)&p_Wh, g_Whi);
        cudaGetSymbolAddress((void**)&p_Wl, g_Wlo);
        cudaGetSymbolAddress((void**)&p_Ah, g_AXhi);
        cudaGetSymbolAddress((void**)&p_Al, g_AXlo);
        cudaGetSymbolAddress((void**)&p_Bh, g_BXhi);
        cudaGetSymbolAddress((void**)&p_Bl, g_BXlo);
        cudaGetSymbolAddress((void**)&p_hh, g_hhi);
        cudaGetSymbolAddress((void**)&p_hl, g_hlo);
        for (int i = 0; i < 3; i++) {
            hhi[i] = (__nv_bfloat16*)(p_hh + (size_t)i * Mn * 128 * 2);
            hlo[i] = (__nv_bfloat16*)(p_hl + (size_t)i * Mn * 128 * 2);
        }
        for (int i = 0; i < 4; i++) {
            Whi[i]  = (__nv_bfloat16*)(p_Wh + (size_t)i * HDn * En * 2);
            Wlo[i]  = (__nv_bfloat16*)(p_Wl + (size_t)i * HDn * En * 2);
            AXhi[i] = (__nv_bfloat16*)(p_Ah + (size_t)i * 128 * En * 2);
            AXlo[i] = (__nv_bfloat16*)(p_Al + (size_t)i * 128 * En * 2);
            BXhi[i] = (__nv_bfloat16*)(p_Bh + (size_t)i * HDn * 128 * 2);
            BXlo[i] = (__nv_bfloat16*)(p_Bl + (size_t)i * HDn * 128 * 2);
        }
    }

    KernT tg_d = tgemm2_kernel<128, 256, 2, 8, 16>;
    KernT tg_h = tgemm2_kernel<32, 128, 1, 8, 4>;
    cudaFuncSetAttribute(tg_d, cudaFuncAttributeMaxDynamicSharedMemorySize, DENSE_SMEM);
    cudaFuncSetAttribute(tg_h, cudaFuncAttributeMaxDynamicSharedMemorySize, H_SMEM);
    cudaFuncSetAttribute(flash_kernel, cudaFuncAttributeMaxDynamicSharedMemorySize, FLASH_SMEM);

    // ---- all input conversions in one batched launch ----
    {
        CvtArgs ca;
        ca.src[0] = x;  ca.hi[0] = xhi; ca.lo[0] = xlo; ca.n4[0] = Mn * En / 4;
        for (int i = 0; i < 4; i++) {
            ca.src[1 + i] = Wp[i]; ca.hi[1 + i] = Whi[i]; ca.lo[1 + i] = Wlo[i];
            ca.n4[1 + i] = HDn * En / 4;
            ca.src[5 + i] = Ap[i]; ca.hi[5 + i] = AXhi[i]; ca.lo[5 + i] = AXlo[i];
            ca.n4[5 + i] = 128 * En / 4;
            ca.src[9 + i] = Bp[i]; ca.hi[9 + i] = BXhi[i]; ca.lo[9 + i] = BXlo[i];
            ca.n4[9 + i] = HDn * 128 / 4;
        }
        cvtb_kernel<<<dim3(256, 1, NCVT), 256>>>(ca);
    }

    GArgs a;
    auto clr = [&]() {
        for (int i = 0; i < 3; i++) {
            a.A2hi[i] = nullptr; a.A2lo[i] = nullptr;
            a.B2hi[i] = nullptr; a.B2lo[i] = nullptr;
            a.bias[i] = nullptr; a.mask[i] = nullptr; a.C[i] = nullptr;
            a.Chi[i] = nullptr; a.Clo[i] = nullptr;
        }
    };

    // ---- h projections (q,k,v): x @ A^T * mask -> split h  (32x128 tiles) ----
    clr();
    for (int i = 0; i < 3; i++) {
        a.A1hi[i] = xhi; a.A1lo[i] = xlo;
        a.B1hi[i] = AXhi[i]; a.B1lo[i] = AXlo[i];
        a.mask[i] = mask; a.Chi[i] = hhi[i]; a.Clo[i] = hlo[i];
    }
    tg_h<<<dim3(1, Mn / 32, 3), 128, H_SMEM>>>(a, Mn, 128, En, 0);

    // ---- fused dense + low-rank q,k,v:  x@W^T (K=2048) + h@BX^T (K=128) ----
    clr();
    for (int i = 0; i < 3; i++) {
        a.A1hi[i] = xhi; a.A1lo[i] = xlo;
        a.B1hi[i] = Whi[i]; a.B1lo[i] = Wlo[i];
        a.A2hi[i] = hhi[i]; a.A2lo[i] = hlo[i];
        a.B2hi[i] = BXhi[i]; a.B2lo[i] = BXlo[i];
        a.bias[i] = bp[i]; a.C[i] = gqkv[i];
    }
    tg_d<<<dim3(HDn / 256, Mn / 128, 3), 512, DENSE_SMEM>>>(a, Mn, HDn, En, 128);

    // ---- RoPE + split (q,k); V split+transpose ----
    {
        int total = Bn * Sn * Hn * (Dn / 4);
        rope_split_kernel<<<(total + 255) / 256, 256>>>(gq, gk, qshi, qslo, kshi, kslo);
        vsplit_kernel<<<dim3(Sn / 32, Dn / 32, Bn * Hn), 256>>>(gv, vthi, vtlo);
    }

    // ---- Attention (tensor cores) -> split o ----
    flash_kernel<<<dim3(Sn / 128, Hn, Bn), 256, FLASH_SMEM>>>(
        qshi, qslo, kshi, kslo, vthi, vtlo, ohi, olo);

    // ---- h for output projection: o @ Ao^T * mask -> split h[0] ----
    clr();
    a.A1hi[0] = ohi; a.A1lo[0] = olo;
    a.B1hi[0] = AXhi[3]; a.B1lo[0] = AXlo[3];
    a.mask[0] = mask; a.Chi[0] = hhi[0]; a.Clo[0] = hlo[0];
    tg_h<<<dim3(1, Mn / 32, 1), 128, H_SMEM>>>(a, Mn, 128, HDn, 0);

    // ---- fused output projection: o@Wo^T (K=2048) + h@Bo^T (K=128) + bo ----
    clr();
    a.A1hi[0] = ohi; a.A1lo[0] = olo;
    a.B1hi[0] = Whi[3]; a.B1lo[0] = Wlo[3];
    a.A2hi[0] = hhi[0]; a.A2lo[0] = hlo[0];
    a.B2hi[0] = BXhi[3]; a.B2lo[0] = BXlo[3];
    a.bias[0] = bp[3]; a.C[0] = out;
    tg_d<<<dim3(En / 256, Mn / 128, 1), 512, DENSE_SMEM>>>(a, Mn, En, HDn, 128);
}

// round 17
// speedup vs baseline: 1.1192x; 1.1192x over previous
#include <cuda_runtime.h>
#include <cuda_bf16.h>
#include <cstdint>

// Problem constants
#define Bn  2
#define Sn  2048
#define En  2048
#define Hn  16
#define Dn  128
#define NEn 8
#define Rn  16
#define HDn 2048
#define Mn  4096            // B*S
#define NEG_BIG -3.0e38f

// ---------------- scratch (device globals: no cudaMalloc allowed) ----------
__device__ __align__(16) float g_q[(size_t)Mn * HDn];
__device__ __align__(16) float g_k[(size_t)Mn * HDn];
__device__ __align__(16) float g_v[(size_t)Mn * HDn];

// bf16 hi/lo split operand storage
__device__ __align__(16) __nv_bfloat16 g_xhi[(size_t)Mn * En],  g_xlo[(size_t)Mn * En];
__device__ __align__(16) __nv_bfloat16 g_Whi[4][(size_t)HDn * En], g_Wlo[4][(size_t)HDn * En];
__device__ __align__(16) __nv_bfloat16 g_AXhi[4][(size_t)128 * En], g_AXlo[4][(size_t)128 * En];
__device__ __align__(16) __nv_bfloat16 g_BXhi[4][(size_t)HDn * 128], g_BXlo[4][(size_t)HDn * 128];
__device__ __align__(16) __nv_bfloat16 g_hhi[3][(size_t)Mn * 128], g_hlo[3][(size_t)Mn * 128];
__device__ __align__(16) __nv_bfloat16 g_ohi[(size_t)Mn * HDn], g_olo[(size_t)Mn * HDn];
// flash operands: q/k rope'd splits [B,S,H,D]; v^T splits [B,H,D,S]
__device__ __align__(16) __nv_bfloat16 g_qshi[(size_t)Mn * HDn], g_qslo[(size_t)Mn * HDn];
__device__ __align__(16) __nv_bfloat16 g_kshi[(size_t)Mn * HDn], g_kslo[(size_t)Mn * HDn];
__device__ __align__(16) __nv_bfloat16 g_vthi[(size_t)Mn * HDn], g_vtlo[(size_t)Mn * HDn];

// ---------------------------------------------------------------------------
// asm helpers
// ---------------------------------------------------------------------------
__device__ __forceinline__ void mma16(float* c, const uint32_t* a, const uint32_t* b) {
    asm("mma.sync.aligned.m16n8k16.row.col.f32.bf16.bf16.f32 "
        "{%0,%1,%2,%3}, {%4,%5,%6,%7}, {%8,%9}, {%0,%1,%2,%3};\n"
        : "+f"(c[0]), "+f"(c[1]), "+f"(c[2]), "+f"(c[3])
        : "r"(a[0]), "r"(a[1]), "r"(a[2]), "r"(a[3]), "r"(b[0]), "r"(b[1]));
}

__device__ __forceinline__ void ldsm4(uint32_t* r, uint32_t addr) {
    asm volatile(
        "ldmatrix.sync.aligned.m8n8.x4.shared.b16 {%0,%1,%2,%3}, [%4];"
        : "=r"(r[0]), "=r"(r[1]), "=r"(r[2]), "=r"(r[3]) : "r"(addr));
}

__device__ __forceinline__ void cp16(uint32_t saddr, const void* gaddr) {
    asm volatile("cp.async.cg.shared.global [%0], [%1], 16;\n" :: "r"(saddr), "l"(gaddr));
}
__device__ __forceinline__ void cp_commit() { asm volatile("cp.async.commit_group;\n"); }
__device__ __forceinline__ void cp_wait0()  { asm volatile("cp.async.wait_group 0;\n"); }

__device__ __forceinline__ float ex2(float x) {
    float r;
    asm("ex2.approx.f32 %0, %1;" : "=f"(r) : "f"(x));
    return r;
}

// split a,b into packed bf16x2 hi and lo fragments
__device__ __forceinline__ void packsplit(float a, float b, uint32_t& hi, uint32_t& lo) {
    __nv_bfloat162 h = __floats2bfloat162_rn(a, b);
    float ra = a - __bfloat162float(h.x);
    float rb = b - __bfloat162float(h.y);
    __nv_bfloat162 l = __floats2bfloat162_rn(ra, rb);
    hi = *(uint32_t*)&h;
    lo = *(uint32_t*)&l;
}

// ---------------------------------------------------------------------------
// batched f32 -> bf16 hi/lo split (grid-stride, z-indexed tensor set)
// ---------------------------------------------------------------------------
#define NCVT 13
struct CvtArgs {
    const float* src[NCVT];
    __nv_bfloat16* hi[NCVT];
    __nv_bfloat16* lo[NCVT];
    int n4[NCVT];
};

__global__ void cvtb_kernel(CvtArgs a)
{
    const int z = blockIdx.z;
    const int n4 = a.n4[z];
    const float4* s = (const float4*)a.src[z];
    uint2* hp = (uint2*)a.hi[z];
    uint2* lp = (uint2*)a.lo[z];
    for (int i = blockIdx.x * blockDim.x + threadIdx.x; i < n4;
         i += gridDim.x * blockDim.x) {
        float4 v = s[i];
        uint32_t h01, l01, h23, l23;
        packsplit(v.x, v.y, h01, l01);
        packsplit(v.z, v.w, h23, l23);
        hp[i] = make_uint2(h01, h23);
        lp[i] = make_uint2(l01, l23);
    }
}

// ---------------------------------------------------------------------------
// tgemm2 (bf16x3, two K-segments): C = A1 @ B1^T  +  A2 @ B2^T
//   Epilogue: +bias, *mask(expert), write float C or split bf16 Chi/Clo.
// BK = 32, 2-stage cp.async, single sync per K-chunk, ldmatrix frags.
// blockIdx.z selects pointer set (batched q/k/v).  (R15-proven config)
// ---------------------------------------------------------------------------
struct GArgs {
    const __nv_bfloat16 *A1hi[3], *A1lo[3], *B1hi[3], *B1lo[3];
    const __nv_bfloat16 *A2hi[3], *A2lo[3], *B2hi[3], *B2lo[3];
    const float *bias[3], *mask[3];
    float* C[3];
    __nv_bfloat16 *Chi[3], *Clo[3];
};

template<int BM, int BN, int MT, int NT, int NW>
__global__ void __launch_bounds__(NW * 32) tgemm2_kernel(
    GArgs g, int M, int N, int K1, int K2)
{
    constexpr int NTHR  = NW * 32;
    constexpr int ROWB  = 80;                 // 40 bf16 per padded row
    constexpr int ABY   = BM * ROWB;
    constexpr int BBY   = BN * ROWB;
    constexpr int BUFB  = 2 * ABY + 2 * BBY;
    constexpr int WROWS = BM / (MT * 16);

    extern __shared__ char smraw[];
    const uint32_t sbase = (uint32_t)__cvta_generic_to_shared(smraw);

    const int z = blockIdx.z;
    const float* bias = g.bias[z];
    const float* mask = g.mask[z];
    float* C = g.C[z];
    __nv_bfloat16* Chi = g.Chi[z];
    __nv_bfloat16* Clo = g.Clo[z];

    const int bm = blockIdx.y * BM;
    const int bn = blockIdx.x * BN;
    const int tid  = threadIdx.x;
    const int lane = tid & 31;
    const int w    = tid >> 5;
    const int wm   = (w % WROWS) * (MT * 16);
    const int wn   = (w / WROWS) * (NT * 8);
    const int grp  = lane >> 2;
    const int qt   = lane & 3;

    const int a_row = ((lane >> 3) & 1) * 8 + (lane & 7);
    const int a_col = (lane >> 4) * 8;
    const int b_row = (lane >> 4) * 8 + (lane & 7);
    const int b_col = ((lane >> 3) & 1) * 8;

    const int nk1 = K1 >> 5;
    const int nk  = nk1 + (K2 >> 5);

    float acc[MT][NT][4];
#pragma unroll
    for (int mt = 0; mt < MT; mt++)
#pragma unroll
        for (int nt = 0; nt < NT; nt++)
#pragma unroll
            for (int e = 0; e < 4; e++) acc[mt][nt][e] = 0.f;

    auto issue = [&](int it, int buf) {
        const __nv_bfloat16 *pAh, *pAl, *pBh, *pBl;
        int kst, k0;
        if (it < nk1) {
            pAh = g.A1hi[z]; pAl = g.A1lo[z]; pBh = g.B1hi[z]; pBl = g.B1lo[z];
            kst = K1; k0 = it << 5;
        } else {
            pAh = g.A2hi[z]; pAl = g.A2lo[z]; pBh = g.B2hi[z]; pBl = g.B2lo[z];
            kst = K2; k0 = (it - nk1) << 5;
        }
        const uint32_t sb = sbase + buf * BUFB;
#pragma unroll
        for (int i = tid; i < BM * 4; i += NTHR) {
            int row = i >> 2, c = i & 3;
            size_t go = (size_t)(bm + row) * kst + k0 + c * 8;
            cp16(sb + row * ROWB + c * 16, pAh + go);
            cp16(sb + ABY + row * ROWB + c * 16, pAl + go);
        }
#pragma unroll
        for (int i = tid; i < BN * 4; i += NTHR) {
            int row = i >> 2, c = i & 3;
            size_t go = (size_t)(bn + row) * kst + k0 + c * 8;
            cp16(sb + 2 * ABY + row * ROWB + c * 16, pBh + go);
            cp16(sb + 2 * ABY + BBY + row * ROWB + c * 16, pBl + go);
        }
        cp_commit();
    };

    issue(0, 0);

    for (int it = 0; it < nk; it++) {
        const int buf = it & 1;
        cp_wait0();
        __syncthreads();
        if (it + 1 < nk) issue(it + 1, buf ^ 1);

        const uint32_t aHi = sbase + buf * BUFB;
        const uint32_t aLo = aHi + ABY;
        const uint32_t bHi = aHi + 2 * ABY;
        const uint32_t bLo = bHi + BBY;

#pragma unroll
        for (int kk = 0; kk < 32; kk += 16) {
            uint32_t afH[MT][4], afL[MT][4];
#pragma unroll
            for (int mt = 0; mt < MT; mt++) {
                uint32_t off = (uint32_t)((wm + mt * 16 + a_row) * 40 + kk + a_col) * 2;
                ldsm4(afH[mt], aHi + off);
                ldsm4(afL[mt], aLo + off);
            }
#pragma unroll
            for (int nb = 0; nb < NT / 2; nb++) {
                uint32_t off = (uint32_t)((wn + nb * 16 + b_row) * 40 + kk + b_col) * 2;
                uint32_t bh[4], bl[4];
                ldsm4(bh, bHi + off);
                ldsm4(bl, bLo + off);
#pragma unroll
                for (int hf = 0; hf < 2; hf++)
#pragma unroll
                    for (int mt = 0; mt < MT; mt++)
                        mma16(acc[mt][nb * 2 + hf], afH[mt], &bl[hf * 2]);
#pragma unroll
                for (int hf = 0; hf < 2; hf++)
#pragma unroll
                    for (int mt = 0; mt < MT; mt++)
                        mma16(acc[mt][nb * 2 + hf], afL[mt], &bh[hf * 2]);
#pragma unroll
                for (int hf = 0; hf < 2; hf++)
#pragma unroll
                    for (int mt = 0; mt < MT; mt++)
                        mma16(acc[mt][nb * 2 + hf], afH[mt], &bh[hf * 2]);
            }
        }
    }

    // epilogue
#pragma unroll
    for (int mt = 0; mt < MT; mt++) {
#pragma unroll
        for (int nt = 0; nt < NT; nt++) {
            int m0 = bm + wm + mt * 16 + grp;
            int n  = bn + wn + nt * 8 + qt * 2;
            float c0 = acc[mt][nt][0], c1 = acc[mt][nt][1];
            float c2 = acc[mt][nt][2], c3 = acc[mt][nt][3];
            if (bias) {
                float b0 = bias[n], b1 = bias[n + 1];
                c0 += b0; c1 += b1; c2 += b0; c3 += b1;
            }
            if (mask) {   // h-GEMM: expert = n>>4 (R=16 contiguous)
                float s0 = mask[(size_t)m0 * NEn + (n >> 4)];
                float s1 = mask[(size_t)(m0 + 8) * NEn + (n >> 4)];
                c0 *= s0; c1 *= s0; c2 *= s1; c3 *= s1;
            }
            if (Chi) {
                uint32_t h0, l0, h1, l1;
                packsplit(c0, c1, h0, l0);
                packsplit(c2, c3, h1, l1);
                *(uint32_t*)&Chi[(size_t)m0 * N + n] = h0;
                *(uint32_t*)&Clo[(size_t)m0 * N + n] = l0;
                *(uint32_t*)&Chi[(size_t)(m0 + 8) * N + n] = h1;
                *(uint32_t*)&Clo[(size_t)(m0 + 8) * N + n] = l1;
            } else {
                *(float2*)&C[(size_t)m0 * N + n] = make_float2(c0, c1);
                *(float2*)&C[(size_t)(m0 + 8) * N + n] = make_float2(c2, c3);
            }
        }
    }
}

using KernT = void(*)(GArgs, int, int, int, int);
constexpr int DENSE_SMEM = 2 * (2 * 128 * 80 + 2 * 128 * 80);   // 81920 B
constexpr int H_SMEM     = 2 * (2 * 32 * 80 + 2 * 128 * 80);    // 51200 B

// ---------------------------------------------------------------------------
// prep_kernel: fused RoPE+split (q,k) AND V split+transpose in one launch.
//   blocks [0, RB)            : rope on q,k (2 freq pairs / thread)
//   blocks [RB, RB + VB)      : vsplit (32x32 transpose tiles)
// ---------------------------------------------------------------------------
#define ROPE_BLOCKS 8192      // Bn*Sn*Hn*(Dn/4) / 256
#define VS_BLOCKS   8192      // (Sn/32) * (Dn/32) * Bn*Hn

__global__ void __launch_bounds__(256) prep_kernel(
    const float* __restrict__ q, const float* __restrict__ k,
    __nv_bfloat16* __restrict__ qhi, __nv_bfloat16* __restrict__ qlo,
    __nv_bfloat16* __restrict__ khi, __nv_bfloat16* __restrict__ klo,
    const float* __restrict__ v,
    __nv_bfloat16* __restrict__ vthi, __nv_bfloat16* __restrict__ vtlo)
{
    __shared__ float tile[32][33];
    const int tid = threadIdx.x;

    if (blockIdx.x < ROPE_BLOCKS) {
        // ---------------- RoPE + split ----------------
        int idx = blockIdx.x * 256 + tid;
        int i2 = (idx & 31) * 2;
        int s  = (idx >> 9) & (Sn - 1);
        const float QSC = 0.12751743f;               // log2(e)/sqrt(128)
        const float L2T = 0.20762050593045952f;      // log2(10000)/64

        float inv0 = exp2f(-(float)i2 * L2T);
        float inv1 = exp2f(-(float)(i2 + 1) * L2T);
        float c0, s0, c1, s1;
        sincosf((float)s * inv0, &s0, &c0);
        sincosf((float)s * inv1, &s1, &c1);

        size_t base = ((size_t)(idx >> 5)) * 128;
        {
            float2 a = *(const float2*)&q[base + i2];
            float2 b = *(const float2*)&q[base + i2 + 64];
            float r0 = (a.x * c0 - b.x * s0) * QSC;
            float r1 = (a.y * c1 - b.y * s1) * QSC;
            float t0 = (b.x * c0 + a.x * s0) * QSC;
            float t1 = (b.y * c1 + a.y * s1) * QSC;
            uint32_t h, l;
            packsplit(r0, r1, h, l);
            *(uint32_t*)&qhi[base + i2] = h;
            *(uint32_t*)&qlo[base + i2] = l;
            packsplit(t0, t1, h, l);
            *(uint32_t*)&qhi[base + i2 + 64] = h;
            *(uint32_t*)&qlo[base + i2 + 64] = l;
        }
        {
            float2 a = *(const float2*)&k[base + i2];
            float2 b = *(const float2*)&k[base + i2 + 64];
            float r0 = a.x * c0 - b.x * s0;
            float r1 = a.y * c1 - b.y * s1;
            float t0 = b.x * c0 + a.x * s0;
            float t1 = b.y * c1 + a.y * s1;
            uint32_t h, l;
            packsplit(r0, r1, h, l);
            *(uint32_t*)&khi[base + i2] = h;
            *(uint32_t*)&klo[base + i2] = l;
            packsplit(t0, t1, h, l);
            *(uint32_t*)&khi[base + i2 + 64] = h;
            *(uint32_t*)&klo[base + i2 + 64] = l;
        }
    } else {
        // ---------------- V split + transpose ----------------
        const int bi = blockIdx.x - ROPE_BLOCKS;
        const int s0i = (bi & 63) * 32;              // Sn/32 = 64 tiles
        const int d0  = ((bi >> 6) & 3) * 32;        // Dn/32 = 4 tiles
        const int bh  = bi >> 8;                     // Bn*Hn = 32
        const int b   = bh >> 4, h = bh & 15;
        const int tx = tid & 31, ty = tid >> 5;

#pragma unroll
        for (int r = 0; r < 4; r++) {
            int s = s0i + ty + r * 8;
            tile[ty + r * 8][tx] = v[(((size_t)b * Sn + s) * Hn + h) * 128 + d0 + tx];
        }
        __syncthreads();

        const int sp = tid & 15;
        const int dd = tid >> 4;
#pragma unroll
        for (int r = 0; r < 2; r++) {
            int d = dd + r * 16;
            float v0 = tile[sp * 2][d];
            float v1 = tile[sp * 2 + 1][d];
            uint32_t hi, lo;
            packsplit(v0, v1, hi, lo);
            size_t o = ((size_t)bh * 128 + d0 + d) * Sn + s0i + sp * 2;
            *(uint32_t*)&vthi[o] = hi;
            *(uint32_t*)&vtlo[o] = lo;
        }
    }
}

// ---------------------------------------------------------------------------
// Flash attention, bf16x3 tensor cores. Single sync per tile. (R15 version)
// ---------------------------------------------------------------------------
#define FQH 0
#define FQL 34816
#define FKH(b) (69632 + (b) * 34816)
#define FKL(b) (FKH(b) + 17408)
#define FVH(b) (139264 + (b) * 36864)
#define FVL(b) (FVH(b) + 18432)
#define FLASH_SMEM 212992

__global__ void __launch_bounds__(256, 1) flash_kernel(
    const __nv_bfloat16* __restrict__ Qhi, const __nv_bfloat16* __restrict__ Qlo,
    const __nv_bfloat16* __restrict__ Khi, const __nv_bfloat16* __restrict__ Klo,
    const __nv_bfloat16* __restrict__ Vthi, const __nv_bfloat16* __restrict__ Vtlo,
    __nv_bfloat16* __restrict__ Ohi, __nv_bfloat16* __restrict__ Olo)
{
    extern __shared__ char smraw[];
    const uint32_t sb = (uint32_t)__cvta_generic_to_shared(smraw);

    const int qTile = gridDim.x - 1 - blockIdx.x;   // heavy CTAs first
    const int q0 = qTile * 128;
    const int h  = blockIdx.y;
    const int b  = blockIdx.z;
    const int tid  = threadIdx.x;
    const int lane = tid & 31;
    const int w    = tid >> 5;
    const int w16  = w * 16;
    const int grp  = lane >> 2;
    const int qt   = lane & 3;

    const int a_row = ((lane >> 3) & 1) * 8 + (lane & 7);
    const int a_col = (lane >> 4) * 8;
    const int b_row = (lane >> 4) * 8 + (lane & 7);
    const int b_col = ((lane >> 3) & 1) * 8;

    auto fillK = [&](int j0, int buf) {
        for (int i = tid; i < 1024; i += 256) {
            int row = i >> 4, c = i & 15;
            size_t gg = (((size_t)b * Sn + j0 + row) * Hn + h) * 128 + c * 8;
            uint32_t so = row * 272 + c * 16;
            cp16(sb + FKH(buf) + so, Khi + gg);
            cp16(sb + FKL(buf) + so, Klo + gg);
        }
    };
    auto fillV = [&](int j0, int buf) {
        for (int i = tid; i < 1024; i += 256) {
            int row = i >> 3, c = i & 7;
            size_t gg = (((size_t)(b * Hn + h)) * 128 + row) * Sn + j0 + c * 8;
            uint32_t so = row * 144 + c * 16;
            cp16(sb + FVH(buf) + so, Vthi + gg);
            cp16(sb + FVL(buf) + so, Vtlo + gg);
        }
    };

    for (int i = tid; i < 2048; i += 256) {
        int row = i >> 4, c = i & 15;
        size_t gg = (((size_t)b * Sn + q0 + row) * Hn + h) * 128 + c * 8;
        uint32_t so = row * 272 + c * 16;
        cp16(sb + FQH + so, Qhi + gg);
        cp16(sb + FQL + so, Qlo + gg);
    }
    fillK(0, 0);
    fillV(0, 0);
    cp_commit();

    float o[16][4];
#pragma unroll
    for (int t = 0; t < 16; t++)
#pragma unroll
        for (int e = 0; e < 4; e++) o[t][e] = 0.f;
    float run_m0 = NEG_BIG, run_m1 = NEG_BIG;
    float run_l0 = 0.f, run_l1 = 0.f;

    const int ntiles = qTile * 2 + 2;
    for (int t = 0; t < ntiles; t++) {
        const int buf = t & 1;
        const int j0 = t * 64;
        cp_wait0();
        __syncthreads();
        if (t + 1 < ntiles) {
            fillK((t + 1) * 64, buf ^ 1);
            fillV((t + 1) * 64, buf ^ 1);
            cp_commit();
        }

        // ---- S = Q K^T (bf16x3) ----
        float s[8][4];
#pragma unroll
        for (int tt = 0; tt < 8; tt++)
#pragma unroll
            for (int e = 0; e < 4; e++) s[tt][e] = 0.f;

        const uint32_t kh = FKH(buf), kl = FKL(buf);
#pragma unroll
        for (int kk = 0; kk < 8; kk++) {
            uint32_t qh[4], ql[4];
            uint32_t qoff = (uint32_t)((w16 + a_row) * 136 + kk * 16 + a_col) * 2;
            ldsm4(qh, sb + FQH + qoff);
            ldsm4(ql, sb + FQL + qoff);
#pragma unroll
            for (int nb = 0; nb < 4; nb++) {
                uint32_t bh[4], bl[4];
                uint32_t boff = (uint32_t)((nb * 16 + b_row) * 136 + kk * 16 + b_col) * 2;
                ldsm4(bh, sb + kh + boff);
                ldsm4(bl, sb + kl + boff);
#pragma unroll
                for (int hf = 0; hf < 2; hf++) {
                    float* c = s[nb * 2 + hf];
                    mma16(c, qh, &bl[hf * 2]);
                    mma16(c, ql, &bh[hf * 2]);
                    mma16(c, qh, &bh[hf * 2]);
                }
            }
        }

        // ---- causal mask ----
        if (j0 >= q0) {
#pragma unroll
            for (int tt = 0; tt < 8; tt++) {
#pragma unroll
                for (int e = 0; e < 4; e++) {
                    int col = j0 + tt * 8 + 2 * qt + (e & 1);
                    int row = q0 + w16 + grp + 8 * (e >> 1);
                    if (col > row) s[tt][e] = NEG_BIG;
                }
            }
        }

        // ---- online softmax (log2e units) ----
        {
            float m0 = NEG_BIG, m1 = NEG_BIG;
#pragma unroll
            for (int tt = 0; tt < 8; tt++) {
                m0 = fmaxf(m0, fmaxf(s[tt][0], s[tt][1]));
                m1 = fmaxf(m1, fmaxf(s[tt][2], s[tt][3]));
            }
            m0 = fmaxf(m0, __shfl_xor_sync(0xffffffffu, m0, 1));
            m0 = fmaxf(m0, __shfl_xor_sync(0xffffffffu, m0, 2));
            m1 = fmaxf(m1, __shfl_xor_sync(0xffffffffu, m1, 1));
            m1 = fmaxf(m1, __shfl_xor_sync(0xffffffffu, m1, 2));
            float nm0 = fmaxf(run_m0, m0), nm1 = fmaxf(run_m1, m1);
            float cr0 = ex2(run_m0 - nm0), cr1 = ex2(run_m1 - nm1);
            run_m0 = nm0; run_m1 = nm1;

            float sum0 = 0.f, sum1 = 0.f;
#pragma unroll
            for (int tt = 0; tt < 8; tt++) {
                s[tt][0] = ex2(s[tt][0] - nm0); sum0 += s[tt][0];
                s[tt][1] = ex2(s[tt][1] - nm0); sum0 += s[tt][1];
                s[tt][2] = ex2(s[tt][2] - nm1); sum1 += s[tt][2];
                s[tt][3] = ex2(s[tt][3] - nm1); sum1 += s[tt][3];
            }
            sum0 += __shfl_xor_sync(0xffffffffu, sum0, 1);
            sum0 += __shfl_xor_sync(0xffffffffu, sum0, 2);
            sum1 += __shfl_xor_sync(0xffffffffu, sum1, 1);
            sum1 += __shfl_xor_sync(0xffffffffu, sum1, 2);
            run_l0 = run_l0 * cr0 + sum0;
            run_l1 = run_l1 * cr1 + sum1;

#pragma unroll
            for (int tt = 0; tt < 16; tt++) {
                o[tt][0] *= cr0; o[tt][1] *= cr0;
                o[tt][2] *= cr1; o[tt][3] *= cr1;
            }
        }

        // ---- O += P V (bf16x3; P from accumulator registers) ----
        const uint32_t vh = FVH(buf), vl = FVL(buf);
#pragma unroll
        for (int k = 0; k < 4; k++) {
            uint32_t ph[4], pl[4];
            packsplit(s[2 * k][0],     s[2 * k][1],     ph[0], pl[0]);
            packsplit(s[2 * k][2],     s[2 * k][3],     ph[1], pl[1]);
            packsplit(s[2 * k + 1][0], s[2 * k + 1][1], ph[2], pl[2]);
            packsplit(s[2 * k + 1][2], s[2 * k + 1][3], ph[3], pl[3]);
#pragma unroll
            for (int nb = 0; nb < 8; nb++) {
                uint32_t bh[4], bl[4];
                uint32_t voff = (uint32_t)((nb * 16 + b_row) * 72 + k * 16 + b_col) * 2;
                ldsm4(bh, sb + vh + voff);
                ldsm4(bl, sb + vl + voff);
#pragma unroll
                for (int hf = 0; hf < 2; hf++) {
                    float* c = o[nb * 2 + hf];
                    mma16(c, ph, &bl[hf * 2]);
                    mma16(c, pl, &bh[hf * 2]);
                    mma16(c, ph, &bh[hf * 2]);
                }
            }
        }
    }

    // ---- epilogue: bf16 hi/lo split, [B,S,H*D] layout ----
    {
        float inv0 = 1.f / run_l0;
        float inv1 = 1.f / run_l1;
        int row0 = q0 + w16 + grp;
        size_t base0 = (((size_t)b * Sn + row0) * Hn + h) * 128 + 2 * qt;
        size_t base1 = (((size_t)b * Sn + row0 + 8) * Hn + h) * 128 + 2 * qt;
#pragma unroll
        for (int tt = 0; tt < 16; tt++) {
            uint32_t h0, l0, h1, l1;
            packsplit(o[tt][0] * inv0, o[tt][1] * inv0, h0, l0);
            packsplit(o[tt][2] * inv1, o[tt][3] * inv1, h1, l1);
            *(uint32_t*)&Ohi[base0 + tt * 8] = h0;
            *(uint32_t*)&Olo[base0 + tt * 8] = l0;
            *(uint32_t*)&Ohi[base1 + tt * 8] = h1;
            *(uint32_t*)&Olo[base1 + tt * 8] = l1;
        }
    }
}

// ---------------------------------------------------------------------------
extern "C" void kernel_launch(void* const* d_in, const int* in_sizes, int n_in,
                              void* d_out, int out_size)
{
    const float* x    = (const float*)d_in[0];
    const float* mask = (const float*)d_in[1];
    const float* Wp[4] = {(const float*)d_in[2], (const float*)d_in[6],
                          (const float*)d_in[10], (const float*)d_in[14]};
    const float* bp[4] = {(const float*)d_in[3], (const float*)d_in[7],
                          (const float*)d_in[11], (const float*)d_in[15]};
    const float* Ap[4] = {(const float*)d_in[4], (const float*)d_in[8],
                          (const float*)d_in[12], (const float*)d_in[16]};
    const float* Bp[4] = {(const float*)d_in[5], (const float*)d_in[9],
                          (const float*)d_in[13], (const float*)d_in[17]};
    float* out = (float*)d_out;

    float *gq, *gk, *gv;
    cudaGetSymbolAddress((void**)&gq, g_q);
    cudaGetSymbolAddress((void**)&gk, g_k);
    cudaGetSymbolAddress((void**)&gv, g_v);
    float* gqkv[3] = {gq, gk, gv};

    __nv_bfloat16 *xhi, *xlo, *ohi, *olo;
    __nv_bfloat16 *Whi[4], *Wlo[4], *AXhi[4], *AXlo[4], *BXhi[4], *BXlo[4];
    __nv_bfloat16 *hhi[3], *hlo[3];
    __nv_bfloat16 *qshi, *qslo, *kshi, *kslo, *vthi, *vtlo;
    {
        char *p;
        cudaGetSymbolAddress((void**)&p, g_xhi); xhi = (__nv_bfloat16*)p;
        cudaGetSymbolAddress((void**)&p, g_xlo); xlo = (__nv_bfloat16*)p;
        cudaGetSymbolAddress((void**)&p, g_ohi); ohi = (__nv_bfloat16*)p;
        cudaGetSymbolAddress((void**)&p, g_olo); olo = (__nv_bfloat16*)p;
        cudaGetSymbolAddress((void**)&p, g_qshi); qshi = (__nv_bfloat16*)p;
        cudaGetSymbolAddress((void**)&p, g_qslo); qslo = (__nv_bfloat16*)p;
        cudaGetSymbolAddress((void**)&p, g_kshi); kshi = (__nv_bfloat16*)p;
        cudaGetSymbolAddress((void**)&p, g_kslo); kslo = (__nv_bfloat16*)p;
        cudaGetSymbolAddress((void**)&p, g_vthi); vthi = (__nv_bfloat16*)p;
        cudaGetSymbolAddress((void**)&p, g_vtlo); vtlo = (__nv_bfloat16*)p;
        char *p_Wh, *p_Wl, *p_Ah, *p_Al, *p_Bh, *p_Bl, *p_hh, *p_hl;
        cudaGetSymbolAddress((void**)&p_Wh, g_Whi);
        cudaGetSymbolAddress((void**)&p_Wl, g_Wlo);
        cudaGetSymbolAddress((void**)&p_Ah, g_AXhi);
        cudaGetSymbolAddress((void**)&p_Al, g_AXlo);
        cudaGetSymbolAddress((void**)&p_Bh, g_BXhi);
        cudaGetSymbolAddress((void**)&p_Bl, g_BXlo);
        cudaGetSymbolAddress((void**)&p_hh, g_hhi);
        cudaGetSymbolAddress((void**)&p_hl, g_hlo);
        for (int i = 0; i < 3; i++) {
            hhi[i] = (__nv_bfloat16*)(p_hh + (size_t)i * Mn * 128 * 2);
            hlo[i] = (__nv_bfloat16*)(p_hl + (size_t)i * Mn * 128 * 2);
        }
        for (int i = 0; i < 4; i++) {
            Whi[i]  = (__nv_bfloat16*)(p_Wh + (size_t)i * HDn * En * 2);
            Wlo[i]  = (__nv_bfloat16*)(p_Wl + (size_t)i * HDn * En * 2);
            AXhi[i] = (__nv_bfloat16*)(p_Ah + (size_t)i * 128 * En * 2);
            AXlo[i] = (__nv_bfloat16*)(p_Al + (size_t)i * 128 * En * 2);
            BXhi[i] = (__nv_bfloat16*)(p_Bh + (size_t)i * HDn * 128 * 2);
            BXlo[i] = (__nv_bfloat16*)(p_Bl + (size_t)i * HDn * 128 * 2);
        }
    }

    KernT tg_d = tgemm2_kernel<128, 128, 2, 8, 8>;
    KernT tg_h = tgemm2_kernel<32, 128, 1, 8, 4>;
    cudaFuncSetAttribute(tg_d, cudaFuncAttributeMaxDynamicSharedMemorySize, DENSE_SMEM);
    cudaFuncSetAttribute(tg_h, cudaFuncAttributeMaxDynamicSharedMemorySize, H_SMEM);
    cudaFuncSetAttribute(flash_kernel, cudaFuncAttributeMaxDynamicSharedMemorySize, FLASH_SMEM);

    // ---- all input conversions in one batched launch ----
    {
        CvtArgs ca;
        ca.src[0] = x;  ca.hi[0] = xhi; ca.lo[0] = xlo; ca.n4[0] = Mn * En / 4;
        for (int i = 0; i < 4; i++) {
            ca.src[1 + i] = Wp[i]; ca.hi[1 + i] = Whi[i]; ca.lo[1 + i] = Wlo[i];
            ca.n4[1 + i] = HDn * En / 4;
            ca.src[5 + i] = Ap[i]; ca.hi[5 + i] = AXhi[i]; ca.lo[5 + i] = AXlo[i];
            ca.n4[5 + i] = 128 * En / 4;
            ca.src[9 + i] = Bp[i]; ca.hi[9 + i] = BXhi[i]; ca.lo[9 + i] = BXlo[i];
            ca.n4[9 + i] = HDn * 128 / 4;
        }
        cvtb_kernel<<<dim3(256, 1, NCVT), 256>>>(ca);
    }

    GArgs a;
    auto clr = [&]() {
        for (int i = 0; i < 3; i++) {
            a.A2hi[i] = nullptr; a.A2lo[i] = nullptr;
            a.B2hi[i] = nullptr; a.B2lo[i] = nullptr;
            a.bias[i] = nullptr; a.mask[i] = nullptr; a.C[i] = nullptr;
            a.Chi[i] = nullptr; a.Clo[i] = nullptr;
        }
    };

    // ---- h projections (q,k,v): x @ A^T * mask -> split h  (32x128 tiles) ----
    clr();
    for (int i = 0; i < 3; i++) {
        a.A1hi[i] = xhi; a.A1lo[i] = xlo;
        a.B1hi[i] = AXhi[i]; a.B1lo[i] = AXlo[i];
        a.mask[i] = mask; a.Chi[i] = hhi[i]; a.Clo[i] = hlo[i];
    }
    tg_h<<<dim3(1, Mn / 32, 3), 128, H_SMEM>>>(a, Mn, 128, En, 0);

    // ---- fused dense + low-rank q,k,v:  x@W^T (K=2048) + h@BX^T (K=128) ----
    clr();
    for (int i = 0; i < 3; i++) {
        a.A1hi[i] = xhi; a.A1lo[i] = xlo;
        a.B1hi[i] = Whi[i]; a.B1lo[i] = Wlo[i];
        a.A2hi[i] = hhi[i]; a.A2lo[i] = hlo[i];
        a.B2hi[i] = BXhi[i]; a.B2lo[i] = BXlo[i];
        a.bias[i] = bp[i]; a.C[i] = gqkv[i];
    }
    tg_d<<<dim3(HDn / 128, Mn / 128, 3), 256, DENSE_SMEM>>>(a, Mn, HDn, En, 128);

    // ---- fused prep: RoPE+split (q,k) + V split/transpose, one launch ----
    prep_kernel<<<ROPE_BLOCKS + VS_BLOCKS, 256>>>(
        gq, gk, qshi, qslo, kshi, kslo, gv, vthi, vtlo);

    // ---- Attention (tensor cores) -> split o ----
    flash_kernel<<<dim3(Sn / 128, Hn, Bn), 256, FLASH_SMEM>>>(
        qshi, qslo, kshi, kslo, vthi, vtlo, ohi, olo);

    // ---- h for output projection: o @ Ao^T * mask -> split h[0] ----
    clr();
    a.A1hi[0] = ohi; a.A1lo[0] = olo;
    a.B1hi[0] = AXhi[3]; a.B1lo[0] = AXlo[3];
    a.mask[0] = mask; a.Chi[0] = hhi[0]; a.Clo[0] = hlo[0];
    tg_h<<<dim3(1, Mn / 32, 1), 128, H_SMEM>>>(a, Mn, 128, HDn, 0);

    // ---- fused output projection: o@Wo^T (K=2048) + h@Bo^T (K=128) + bo ----
    clr();
    a.A1hi[0] = ohi; a.A1lo[0] = olo;
    a.B1hi[0] = Whi[3]; a.B1lo[0] = Wlo[3];
    a.A2hi[0] = hhi[0]; a.A2lo[0] = hlo[0];
    a.B2hi[0] = BXhi[3]; a.B2lo[0] = BXlo[3];
    a.bias[0] = bp[3]; a.C[0] = out;
    tg_d<<<dim3(En / 128, Mn / 128, 1), 256, DENSE_SMEM>>>(a, Mn, En, HDn, 128);
}